// round 15
// baseline (speedup 1.0000x reference)
#include <cuda_runtime.h>
#include <cuda_bf16.h>
#include <math.h>
#include <cstdint>

// ---------------------------------------------------------------------------
// GCN2: h1 = relu(adj @ (x @ gc1_w) + gc1_b)          [208, 8192]
//       h2 = relu(adj @ (h1 @ gc2_w) + gc2_b)         [208, 64]
//       v  = relu(fc1_w @ h2.flat + fc1_b)            [128]
//       v  = relu(fc2_w @ v + fc2_b)                  [32]
//       out = sigmoid(fc3_w @ v + fc3_b)              [1]
//
// GEMM1 on HMMA (mma.sync bf16, 3-term hi/lo split), BN=64, 2 CTAs/SM.
// ---------------------------------------------------------------------------

#define M_NODES 208
#define M_PAD   256
#define NFEAT   8192
#define NHID    8192
#define NCLASS  64
#define G3_SPLIT 16

// Scratch (no allocation allowed)
__device__ float g_s1[M_NODES * NHID];
__device__ float g_h1[M_NODES * NHID];
__device__ float g_s2[M_NODES * NCLASS];
__device__ float g_h2[M_NODES * NCLASS];
__device__ float g_v1[128];
__device__ float g_p3[G3_SPLIT * M_NODES * NCLASS];

__device__ __align__(16) __nv_bfloat16 g_Ahi[M_PAD * NFEAT];   // 4 MB
__device__ __align__(16) __nv_bfloat16 g_Alo[M_PAD * NFEAT];   // 4 MB

// ============================================================================
// helpers
// ============================================================================
__device__ __forceinline__ uint32_t smem_to_u32(const void* p) {
    uint32_t a;
    asm("{ .reg .u64 t; cvta.to.shared.u64 t, %1; cvt.u32.u64 %0, t; }"
        : "=r"(a) : "l"(p));
    return a;
}

__device__ __forceinline__ void ldsm4(uint32_t (&r)[4], uint32_t addr) {
    asm volatile("ldmatrix.sync.aligned.m8n8.x4.shared.b16 {%0,%1,%2,%3}, [%4];"
                 : "=r"(r[0]), "=r"(r[1]), "=r"(r[2]), "=r"(r[3]) : "r"(addr));
}
__device__ __forceinline__ void ldsm4t(uint32_t (&r)[4], uint32_t addr) {
    asm volatile("ldmatrix.sync.aligned.m8n8.x4.trans.shared.b16 {%0,%1,%2,%3}, [%4];"
                 : "=r"(r[0]), "=r"(r[1]), "=r"(r[2]), "=r"(r[3]) : "r"(addr));
}
__device__ __forceinline__ void mma_bf16(float (&d)[4], const uint32_t (&a)[4],
                                         uint32_t b0, uint32_t b1) {
    asm volatile(
        "mma.sync.aligned.m16n8k16.row.col.f32.bf16.bf16.f32 "
        "{%0,%1,%2,%3}, {%4,%5,%6,%7}, {%8,%9}, {%0,%1,%2,%3};"
        : "+f"(d[0]), "+f"(d[1]), "+f"(d[2]), "+f"(d[3])
        : "r"(a[0]), "r"(a[1]), "r"(a[2]), "r"(a[3]), "r"(b0), "r"(b1));
}
__device__ __forceinline__ void sts128(uint32_t addr, uint4 v) {
    asm volatile("st.shared.v4.b32 [%0], {%1,%2,%3,%4};"
                 :: "r"(addr), "r"(v.x), "r"(v.y), "r"(v.z), "r"(v.w));
}

__device__ __forceinline__ uint32_t bits2(__nv_bfloat162 v) {
    return *reinterpret_cast<uint32_t*>(&v);
}

// split 8 fp32 -> bf16 hi chunk (16B) + bf16 lo chunk (16B), lo exact residual
__device__ __forceinline__ void split8(float4 p, float4 q, uint4& h, uint4& l) {
    __nv_bfloat162 h0 = __floats2bfloat162_rn(p.x, p.y);
    __nv_bfloat162 h1 = __floats2bfloat162_rn(p.z, p.w);
    __nv_bfloat162 h2 = __floats2bfloat162_rn(q.x, q.y);
    __nv_bfloat162 h3 = __floats2bfloat162_rn(q.z, q.w);
    __nv_bfloat162 l0 = __floats2bfloat162_rn(p.x - __bfloat162float(h0.x),
                                              p.y - __bfloat162float(h0.y));
    __nv_bfloat162 l1 = __floats2bfloat162_rn(p.z - __bfloat162float(h1.x),
                                              p.w - __bfloat162float(h1.y));
    __nv_bfloat162 l2 = __floats2bfloat162_rn(q.x - __bfloat162float(h2.x),
                                              q.y - __bfloat162float(h2.y));
    __nv_bfloat162 l3 = __floats2bfloat162_rn(q.z - __bfloat162float(h3.x),
                                              q.w - __bfloat162float(h3.y));
    h = make_uint4(bits2(h0), bits2(h1), bits2(h2), bits2(h3));
    l = make_uint4(bits2(l0), bits2(l1), bits2(l2), bits2(l3));
}

// ============================================================================
// convx: x [208, 8192] fp32 -> A_hi/A_lo [256, 8192] bf16 (rows >= 208 zero)
// ============================================================================
__global__ void __launch_bounds__(256, 4)
convx_kernel(const float* __restrict__ x,
             __nv_bfloat16* __restrict__ Ah, __nv_bfloat16* __restrict__ Al)
{
    int u = blockIdx.x * 256 + threadIdx.x;
    int m = u >> 12;
    int c = (u & 4095) * 2;
    float v0 = 0.f, v1 = 0.f;
    if (m < M_NODES) {
        v0 = x[(size_t)m * NFEAT + c];
        v1 = x[(size_t)m * NFEAT + c + 1];
    }
    __nv_bfloat16 h0 = __float2bfloat16(v0);
    __nv_bfloat16 h1 = __float2bfloat16(v1);
    __nv_bfloat16 l0 = __float2bfloat16(v0 - __bfloat162float(h0));
    __nv_bfloat16 l1 = __float2bfloat16(v1 - __bfloat162float(h1));
    size_t o = (size_t)m * NFEAT + c;
    *(__nv_bfloat162*)(Ah + o) = __halves2bfloat162(h0, h1);
    *(__nv_bfloat162*)(Al + o) = __halves2bfloat162(l0, l1);
}

// ============================================================================
// HMMA GEMM1: C[208,8192] = A[208,8192] @ W[8192,8192]
// D = Ahi*Whi + Alo*Whi + Ahi*Wlo. BM=128 BN=64 BK=32, 256 thr (4m x 2n warps,
// warp tile 32x32). 2 CTAs/SM (stage 28672 B x 2 = 57344 B/CTA).
// grid (2, 128): adjacent CTAs share the same W slice -> L2 reuse.
// ============================================================================
#define NKT    256
#define ST_ALO 10240u
#define ST_BHI 20480u
#define ST_BLO 24576u
#define STAGE  28672u
#define G1_SMEM (2 * 28672)

__global__ void __launch_bounds__(256, 2)
hmma_gemm1_kernel(const __nv_bfloat16* __restrict__ Ahi,
                  const __nv_bfloat16* __restrict__ Alo,
                  const float* __restrict__ W,
                  float* __restrict__ C)
{
    extern __shared__ char smemraw[];
    const uint32_t sbase = smem_to_u32(smemraw);

    const int tid  = threadIdx.x;
    const int lane = tid & 31;
    const int wid  = tid >> 5;
    const int wm   = wid & 3;       // 4 warps in m (32 rows each)
    const int wn   = wid >> 2;      // 2 warps in n (32 cols each)
    const int m0   = blockIdx.x * 128;
    const int n0   = blockIdx.y * 64;

    // A: 512 uint4 per (hi|lo) tile -> 2 slots/thread each
    const int ar0 = tid >> 2, ac0 = tid & 3;
    const int ar1 = ar0 + 64;
    const __nv_bfloat16* pAh0 = Ahi + (size_t)(m0 + ar0) * NFEAT + ac0 * 8;
    const __nv_bfloat16* pAh1 = Ahi + (size_t)(m0 + ar1) * NFEAT + ac0 * 8;
    const __nv_bfloat16* pAl0 = Alo + (size_t)(m0 + ar0) * NFEAT + ac0 * 8;
    const __nv_bfloat16* pAl1 = Alo + (size_t)(m0 + ar1) * NFEAT + ac0 * 8;
    const uint32_t aw0 = (uint32_t)(ar0 * 80 + ac0 * 16);
    const uint32_t aw1 = aw0 + 64 * 80;

    // B: 32 k-rows x 64 fp32 = 2048 fp32 -> 8 fp32 (1 slot) per thread
    const int bk = tid >> 3, bn = tid & 7;
    const float* pB = W + (size_t)bk * NHID + n0 + bn * 8;
    const uint32_t bw = (uint32_t)(bk * 128 + ((bn ^ (bk & 7)) << 4));

    // ldmatrix addresses (offsets within a stage)
    uint32_t adA[2], adB[2];
#pragma unroll
    for (int mf = 0; mf < 2; mf++)
        adA[mf] = (uint32_t)((wm * 32 + mf * 16 + (lane & 15)) * 80 + (lane >> 4) * 16);
    {
        const int krb = (lane & 7) + ((lane >> 4) << 3);
#pragma unroll
        for (int g = 0; g < 2; g++) {
            int nch = wn * 4 + g * 2 + ((lane >> 3) & 1);
            adB[g] = (uint32_t)(krb * 128 + ((nch ^ (krb & 7)) << 4));
        }
    }

    float acc[2][4][4];
#pragma unroll
    for (int i = 0; i < 2; i++)
#pragma unroll
        for (int j = 0; j < 4; j++)
#pragma unroll
            for (int q = 0; q < 4; q++) acc[i][j][q] = 0.f;

    uint4  ra[4];
    float4 rb[2];

    auto load_regs = [&]() {
        ra[0] = *(const uint4*)pAh0;  ra[1] = *(const uint4*)pAh1;
        ra[2] = *(const uint4*)pAl0;  ra[3] = *(const uint4*)pAl1;
        rb[0] = *(const float4*)pB;   rb[1] = *(const float4*)(pB + 4);
        pAh0 += 32; pAh1 += 32; pAl0 += 32; pAl1 += 32;
        pB += (size_t)32 * NHID;
    };

    auto store_smem = [&](uint32_t buf) {
        const uint32_t sb = sbase + buf * STAGE;
        sts128(sb + aw0, ra[0]);
        sts128(sb + aw1, ra[1]);
        sts128(sb + ST_ALO + aw0, ra[2]);
        sts128(sb + ST_ALO + aw1, ra[3]);
        uint4 h, l;
        split8(rb[0], rb[1], h, l);
        sts128(sb + ST_BHI + bw, h);
        sts128(sb + ST_BLO + bw, l);
    };

    load_regs();
    store_smem(0);
    __syncthreads();

    uint32_t buf = 0;
    for (int t = 0; t < NKT; t++) {
        const bool more = (t + 1 < NKT);
        if (more) load_regs();

        const uint32_t sb = sbase + buf * STAGE;
#pragma unroll
        for (int s = 0; s < 2; s++) {
            uint32_t ah[2][4], al[2][4];
            ldsm4(ah[0], sb + adA[0] + s * 32);
            ldsm4(ah[1], sb + adA[1] + s * 32);
            ldsm4(al[0], sb + ST_ALO + adA[0] + s * 32);
            ldsm4(al[1], sb + ST_ALO + adA[1] + s * 32);
#pragma unroll
            for (int g = 0; g < 2; g++) {
                uint32_t bh[4], bl[4];
                ldsm4t(bh, sb + ST_BHI + adB[g] + s * 2048);
                ldsm4t(bl, sb + ST_BLO + adB[g] + s * 2048);
#pragma unroll
                for (int mf = 0; mf < 2; mf++) {
                    mma_bf16(acc[mf][2 * g],     ah[mf], bh[0], bh[2]);
                    mma_bf16(acc[mf][2 * g],     al[mf], bh[0], bh[2]);
                    mma_bf16(acc[mf][2 * g],     ah[mf], bl[0], bl[2]);
                    mma_bf16(acc[mf][2 * g + 1], ah[mf], bh[1], bh[3]);
                    mma_bf16(acc[mf][2 * g + 1], al[mf], bh[1], bh[3]);
                    mma_bf16(acc[mf][2 * g + 1], ah[mf], bl[1], bl[3]);
                }
            }
        }

        if (more) {
            store_smem(buf ^ 1u);
            __syncthreads();
            buf ^= 1u;
        }
    }

    const int er = lane >> 2;
    const int ec = (lane & 3) * 2;
#pragma unroll
    for (int mf = 0; mf < 2; mf++) {
        const int mb = m0 + wm * 32 + mf * 16 + er;
#pragma unroll
        for (int j = 0; j < 4; j++) {
            const int n = n0 + wn * 32 + j * 8 + ec;
            if (mb < M_NODES)
                *(float2*)(C + (size_t)mb * NHID + n) =
                    make_float2(acc[mf][j][0], acc[mf][j][1]);
            if (mb + 8 < M_NODES)
                *(float2*)(C + (size_t)(mb + 8) * NHID + n) =
                    make_float2(acc[mf][j][2], acc[mf][j][3]);
        }
    }
}

// ============================================================================
// GEMM2: h1 = relu(adj[208,208] @ s1[208,8192] + gc1_b)
// Smem-resident rank-1: adj strip [104][208] + s1 tile [208][64].
// ============================================================================
#define G2_SMEM (104 * 208 * 4 + 208 * 64 * 4)   // 139776 B

__global__ void __launch_bounds__(256, 1)
gemm2_kernel(const float* __restrict__ adj, const float* __restrict__ s1,
             const float* __restrict__ bias, float* __restrict__ h1)
{
    extern __shared__ float g2s[];
    float* adjs = g2s;                    // [104][208]
    float* s1s  = g2s + 104 * 208;        // [208][64]

    const int tid = threadIdx.x;
    const int n0 = blockIdx.x * 64;
    const int m0 = blockIdx.y * 104;

    for (int idx = tid; idx < 208 * 16; idx += 256) {
        int r = idx >> 4, c = (idx & 15) * 4;
        *(float4*)(s1s + r * 64 + c) =
            *(const float4*)(s1 + (size_t)r * NHID + n0 + c);
    }
    for (int idx = tid; idx < 104 * 52; idx += 256) {
        int r = idx / 52, c = (idx % 52) * 4;
        *(float4*)(adjs + r * 208 + c) =
            *(const float4*)(adj + (size_t)(m0 + r) * M_NODES + c);
    }
    __syncthreads();

    const int tm = tid >> 5;
    const int tn = tid & 31;

    float acc[13][2];
#pragma unroll
    for (int i = 0; i < 13; i++) { acc[i][0] = 0.f; acc[i][1] = 0.f; }

    const float* abase = adjs + tm * 13 * 208;
    const float* sbase = s1s + tn * 2;

#pragma unroll 4
    for (int k = 0; k < M_NODES; k++) {
        const float2 sv = *(const float2*)(sbase + k * 64);
#pragma unroll
        for (int i = 0; i < 13; i++) {
            const float a = abase[i * 208 + k];
            acc[i][0] = fmaf(a, sv.x, acc[i][0]);
            acc[i][1] = fmaf(a, sv.y, acc[i][1]);
        }
    }

    const float b0 = bias[n0 + tn * 2];
    const float b1 = bias[n0 + tn * 2 + 1];
#pragma unroll
    for (int i = 0; i < 13; i++) {
        const int m = m0 + tm * 13 + i;
        float v0 = acc[i][0] + b0;
        float v1 = acc[i][1] + b1;
        v0 = v0 > 0.f ? v0 : 0.f;
        v1 = v1 > 0.f ? v1 : 0.f;
        *(float2*)(h1 + (size_t)m * NHID + n0 + tn * 2) = make_float2(v0, v1);
    }
}

// ---------------------------------------------------------------------------
// GEMM3 split-K: 8 m-rows per block, h1 staged in smem, W float4 loads.
// grid (26, 16), 256 thr = 16 k-slices x 16 n-quads.
// ---------------------------------------------------------------------------
__global__ void __launch_bounds__(256, 3)
gemm3_split_kernel(const float* __restrict__ h1, const float* __restrict__ w2,
                   float* __restrict__ p3)
{
    __shared__ float hs[8][512];          // 16 KB
    __shared__ float red[16][8][64];      // 32 KB

    const int t  = threadIdx.x;
    const int tn = t & 15;
    const int tk = t >> 4;
    const int mb = blockIdx.x * 8;
    const int kc = blockIdx.y;
    const int k0 = kc * 512;

    // stage h1 block [8][512]
#pragma unroll
    for (int j = 0; j < 4; j++) {
        int idx = t + j * 256;            // 0..1023
        int r = idx >> 7, c = (idx & 127) * 4;
        *(float4*)&hs[r][c] =
            *(const float4*)(h1 + (size_t)(mb + r) * NHID + k0 + c);
    }
    __syncthreads();

    float acc[8][4];
#pragma unroll
    for (int m = 0; m < 8; m++)
#pragma unroll
        for (int j = 0; j < 4; j++) acc[m][j] = 0.f;

    const int kb = tk * 32;
#pragma unroll 4
    for (int kk = 0; kk < 32; kk++) {
        const float4 w = *(const float4*)(w2 + (size_t)(k0 + kb + kk) * NCLASS + tn * 4);
#pragma unroll
        for (int m = 0; m < 8; m++) {
            const float h = hs[m][kb + kk];
            acc[m][0] = fmaf(h, w.x, acc[m][0]);
            acc[m][1] = fmaf(h, w.y, acc[m][1]);
            acc[m][2] = fmaf(h, w.z, acc[m][2]);
            acc[m][3] = fmaf(h, w.w, acc[m][3]);
        }
    }

#pragma unroll
    for (int m = 0; m < 8; m++)
        *(float4*)&red[tk][m][tn * 4] =
            make_float4(acc[m][0], acc[m][1], acc[m][2], acc[m][3]);
    __syncthreads();

#pragma unroll
    for (int o = t; o < 512; o += 256) {
        const int m = o >> 6, n = o & 63;
        float s = 0.f;
#pragma unroll
        for (int p = 0; p < 16; p++) s += red[p][m][n];
        p3[(size_t)kc * (M_NODES * NCLASS) + (size_t)(mb + m) * NCLASS + n] = s;
    }
}

__global__ void __launch_bounds__(256, 4)
gemm3_reduce_kernel(const float* __restrict__ p3, float* __restrict__ out)
{
    const int i = blockIdx.x * 256 + threadIdx.x;
    if (i >= M_NODES * NCLASS) return;
    float s = 0.f;
#pragma unroll
    for (int p = 0; p < G3_SPLIT; p++)
        s += p3[(size_t)p * (M_NODES * NCLASS) + i];
    out[i] = s;
}

// ---------------------------------------------------------------------------
// GEMM4: h2 = relu(adj[208,208] @ s2[208,64] + b2[64])
// ---------------------------------------------------------------------------
__global__ void __launch_bounds__(256, 4)
gemm4_kernel(const float* __restrict__ adj, const float* __restrict__ s2,
             const float* __restrict__ b, float* __restrict__ h2)
{
    const int t = threadIdx.x;
    const int n = t & 63;
    const int m = blockIdx.x * 4 + (t >> 6);

    float acc = 0.f;
    const float* ar = adj + (size_t)m * M_NODES;
#pragma unroll 8
    for (int k = 0; k < M_NODES; k++)
        acc = fmaf(ar[k], s2[(size_t)k * NCLASS + n], acc);

    float v = acc + b[n];
    h2[(size_t)m * NCLASS + n] = v > 0.f ? v : 0.f;
}

// ---------------------------------------------------------------------------
// FC1: v1[128] = relu(fc1_w[128,13312] @ h2.flat + fc1_b)
// ---------------------------------------------------------------------------
__global__ void __launch_bounds__(256, 1)
fc1_kernel(const float* __restrict__ w, const float* __restrict__ b,
           const float* __restrict__ h2, float* __restrict__ v1)
{
    const int r = blockIdx.x;
    const int t = threadIdx.x;
    const float* wr = w + (size_t)r * (M_NODES * NCLASS);

    float p = 0.f;
    for (int i = t; i < M_NODES * NCLASS; i += 256)
        p = fmaf(wr[i], h2[i], p);

    __shared__ float red[256];
    red[t] = p;
    __syncthreads();
#pragma unroll
    for (int s = 128; s > 0; s >>= 1) {
        if (t < s) red[t] += red[t + s];
        __syncthreads();
    }
    if (t == 0) {
        float v = red[0] + b[r];
        v1[r] = v > 0.f ? v : 0.f;
    }
}

// ---------------------------------------------------------------------------
// Head
// ---------------------------------------------------------------------------
__global__ void __launch_bounds__(128, 1)
head_kernel(const float* __restrict__ fc2w, const float* __restrict__ fc2b,
            const float* __restrict__ fc3w, const float* __restrict__ fc3b,
            const float* __restrict__ v1, float* __restrict__ out)
{
    __shared__ float v1s[128];
    __shared__ float v2s[32];
    const int t = threadIdx.x;

    v1s[t] = v1[t];
    __syncthreads();

    if (t < 32) {
        float a = 0.f;
#pragma unroll 4
        for (int j = 0; j < 128; j++)
            a = fmaf(fc2w[t * 128 + j], v1s[j], a);
        a += fc2b[t];
        v2s[t] = a > 0.f ? a : 0.f;
    }
    __syncthreads();

    if (t == 0) {
        float s = fc3b[0];
#pragma unroll
        for (int i = 0; i < 32; i++)
            s = fmaf(fc3w[i], v2s[i], s);
        out[0] = 1.0f / (1.0f + expf(-s));
    }
}

// ---------------------------------------------------------------------------
// Launch
// ---------------------------------------------------------------------------
extern "C" void kernel_launch(void* const* d_in, const int* in_sizes, int n_in,
                              void* d_out, int out_size)
{
    (void)in_sizes; (void)n_in; (void)out_size;

    const float* x     = (const float*)d_in[0];
    const float* adj   = (const float*)d_in[1];
    const float* gc1_w = (const float*)d_in[2];
    const float* gc1_b = (const float*)d_in[3];
    const float* gc2_w = (const float*)d_in[4];
    const float* gc2_b = (const float*)d_in[5];
    const float* fc1_w = (const float*)d_in[6];
    const float* fc1_b = (const float*)d_in[7];
    const float* fc2_w = (const float*)d_in[8];
    const float* fc2_b = (const float*)d_in[9];
    const float* fc3_w = (const float*)d_in[10];
    const float* fc3_b = (const float*)d_in[11];
    float* out = (float*)d_out;

    float *s1, *h1, *s2, *h2, *v1, *p3;
    __nv_bfloat16 *Ahi, *Alo;
    cudaGetSymbolAddress((void**)&s1, g_s1);
    cudaGetSymbolAddress((void**)&h1, g_h1);
    cudaGetSymbolAddress((void**)&s2, g_s2);
    cudaGetSymbolAddress((void**)&h2, g_h2);
    cudaGetSymbolAddress((void**)&v1, g_v1);
    cudaGetSymbolAddress((void**)&p3, g_p3);
    cudaGetSymbolAddress((void**)&Ahi, g_Ahi);
    cudaGetSymbolAddress((void**)&Alo, g_Alo);

    cudaFuncSetAttribute(hmma_gemm1_kernel,
                         cudaFuncAttributeMaxDynamicSharedMemorySize, G1_SMEM);
    cudaFuncSetAttribute(gemm2_kernel,
                         cudaFuncAttributeMaxDynamicSharedMemorySize, G2_SMEM);

    // split x -> bf16 hi/lo (padded to 256 rows)
    convx_kernel<<<(M_PAD * NFEAT / 2) / 256, 256>>>(x, Ahi, Alo);

    // s1 = x @ gc1_w  (HMMA, 3-term bf16 split; W split in-kernel)
    hmma_gemm1_kernel<<<dim3(2, NHID / 64), 256, G1_SMEM>>>(Ahi, Alo, gc1_w, s1);

    // h1 = relu(adj @ s1 + gc1_b)  (smem-resident rank-1)
    gemm2_kernel<<<dim3(NHID / 64, 2), 256, G2_SMEM>>>(adj, s1, gc1_b, h1);

    // s2 = h1 @ gc2_w  (split-K + reduce)
    gemm3_split_kernel<<<dim3(M_NODES / 8, G3_SPLIT), 256>>>(h1, gc2_w, p3);
    gemm3_reduce_kernel<<<(M_NODES * NCLASS + 255) / 256, 256>>>(p3, s2);
    // h2 = relu(adj @ s2 + gc2_b)
    gemm4_kernel<<<M_NODES / 4, 256>>>(adj, s2, gc2_b, h2);
    // v1 = relu(fc1_w @ h2.flat + fc1_b)
    fc1_kernel<<<128, 256>>>(fc1_w, fc1_b, h2, v1);
    // out = sigmoid(fc3 @ relu(fc2 @ v1 + b2) + b3)
    head_kernel<<<1, 128>>>(fc2_w, fc2_b, fc3_w, fc3_b, v1, out);
}

// round 16
// speedup vs baseline: 1.5417x; 1.5417x over previous
#include <cuda_runtime.h>
#include <cuda_bf16.h>
#include <math.h>
#include <cstdint>

// ---------------------------------------------------------------------------
// GCN2: h1 = relu(adj @ (x @ gc1_w) + gc1_b)          [208, 8192]
//       h2 = relu(adj @ (h1 @ gc2_w) + gc2_b)         [208, 64]
//       v  = relu(fc1_w @ h2.flat + fc1_b)            [128]
//       v  = relu(fc2_w @ v + fc2_b)                  [32]
//       out = sigmoid(fc3_w @ v + fc3_b)              [1]
//
// GEMM1 on HMMA (mma.sync bf16, 3-term hi/lo split), BM=128 BN=128,
// term-major MMA ordering (dependent MMAs 16 apart, not back-to-back).
// ---------------------------------------------------------------------------

#define M_NODES 208
#define M_PAD   256
#define NFEAT   8192
#define NHID    8192
#define NCLASS  64
#define G3_SPLIT 16

// Scratch (no allocation allowed)
__device__ float g_s1[M_NODES * NHID];
__device__ float g_h1[M_NODES * NHID];
__device__ float g_s2[M_NODES * NCLASS];
__device__ float g_h2[M_NODES * NCLASS];
__device__ float g_v1[128];
__device__ float g_p3[G3_SPLIT * M_NODES * NCLASS];

__device__ __align__(16) __nv_bfloat16 g_Ahi[M_PAD * NFEAT];   // 4 MB
__device__ __align__(16) __nv_bfloat16 g_Alo[M_PAD * NFEAT];   // 4 MB

// ============================================================================
// helpers
// ============================================================================
__device__ __forceinline__ uint32_t smem_to_u32(const void* p) {
    uint32_t a;
    asm("{ .reg .u64 t; cvta.to.shared.u64 t, %1; cvt.u32.u64 %0, t; }"
        : "=r"(a) : "l"(p));
    return a;
}

__device__ __forceinline__ void ldsm4(uint32_t (&r)[4], uint32_t addr) {
    asm volatile("ldmatrix.sync.aligned.m8n8.x4.shared.b16 {%0,%1,%2,%3}, [%4];"
                 : "=r"(r[0]), "=r"(r[1]), "=r"(r[2]), "=r"(r[3]) : "r"(addr));
}
__device__ __forceinline__ void ldsm4t(uint32_t (&r)[4], uint32_t addr) {
    asm volatile("ldmatrix.sync.aligned.m8n8.x4.trans.shared.b16 {%0,%1,%2,%3}, [%4];"
                 : "=r"(r[0]), "=r"(r[1]), "=r"(r[2]), "=r"(r[3]) : "r"(addr));
}
// NOTE: not volatile — pure computation; lets ptxas schedule MMAs.
__device__ __forceinline__ void mma_bf16(float (&d)[4], const uint32_t (&a)[4],
                                         uint32_t b0, uint32_t b1) {
    asm("mma.sync.aligned.m16n8k16.row.col.f32.bf16.bf16.f32 "
        "{%0,%1,%2,%3}, {%4,%5,%6,%7}, {%8,%9}, {%0,%1,%2,%3};"
        : "+f"(d[0]), "+f"(d[1]), "+f"(d[2]), "+f"(d[3])
        : "r"(a[0]), "r"(a[1]), "r"(a[2]), "r"(a[3]), "r"(b0), "r"(b1));
}
__device__ __forceinline__ void sts128(uint32_t addr, uint4 v) {
    asm volatile("st.shared.v4.b32 [%0], {%1,%2,%3,%4};"
                 :: "r"(addr), "r"(v.x), "r"(v.y), "r"(v.z), "r"(v.w));
}

__device__ __forceinline__ uint32_t bits2(__nv_bfloat162 v) {
    return *reinterpret_cast<uint32_t*>(&v);
}

// split 8 fp32 -> bf16 hi chunk (16B) + bf16 lo chunk (16B), lo exact residual
__device__ __forceinline__ void split8(float4 p, float4 q, uint4& h, uint4& l) {
    __nv_bfloat162 h0 = __floats2bfloat162_rn(p.x, p.y);
    __nv_bfloat162 h1 = __floats2bfloat162_rn(p.z, p.w);
    __nv_bfloat162 h2 = __floats2bfloat162_rn(q.x, q.y);
    __nv_bfloat162 h3 = __floats2bfloat162_rn(q.z, q.w);
    __nv_bfloat162 l0 = __floats2bfloat162_rn(p.x - __bfloat162float(h0.x),
                                              p.y - __bfloat162float(h0.y));
    __nv_bfloat162 l1 = __floats2bfloat162_rn(p.z - __bfloat162float(h1.x),
                                              p.w - __bfloat162float(h1.y));
    __nv_bfloat162 l2 = __floats2bfloat162_rn(q.x - __bfloat162float(h2.x),
                                              q.y - __bfloat162float(h2.y));
    __nv_bfloat162 l3 = __floats2bfloat162_rn(q.z - __bfloat162float(h3.x),
                                              q.w - __bfloat162float(h3.y));
    h = make_uint4(bits2(h0), bits2(h1), bits2(h2), bits2(h3));
    l = make_uint4(bits2(l0), bits2(l1), bits2(l2), bits2(l3));
}

// ============================================================================
// convx: x [208, 8192] fp32 -> A_hi/A_lo [256, 8192] bf16 (rows >= 208 zero)
// ============================================================================
__global__ void __launch_bounds__(256, 4)
convx_kernel(const float* __restrict__ x,
             __nv_bfloat16* __restrict__ Ah, __nv_bfloat16* __restrict__ Al)
{
    int u = blockIdx.x * 256 + threadIdx.x;
    int m = u >> 12;
    int c = (u & 4095) * 2;
    float v0 = 0.f, v1 = 0.f;
    if (m < M_NODES) {
        v0 = x[(size_t)m * NFEAT + c];
        v1 = x[(size_t)m * NFEAT + c + 1];
    }
    __nv_bfloat16 h0 = __float2bfloat16(v0);
    __nv_bfloat16 h1 = __float2bfloat16(v1);
    __nv_bfloat16 l0 = __float2bfloat16(v0 - __bfloat162float(h0));
    __nv_bfloat16 l1 = __float2bfloat16(v1 - __bfloat162float(h1));
    size_t o = (size_t)m * NFEAT + c;
    *(__nv_bfloat162*)(Ah + o) = __halves2bfloat162(h0, h1);
    *(__nv_bfloat162*)(Al + o) = __halves2bfloat162(l0, l1);
}

// ============================================================================
// HMMA GEMM1: C[208,8192] = A[208,8192] @ W[8192,8192]
// D = Ahi*Whi + Alo*Whi + Ahi*Wlo. BM=128 BN=128 BK=32, 256 thr (4x2 warps).
// Inner loop is TERM-MAJOR: all 16 MMAs of one term before the next, so
// same-accumulator MMAs are 16 apart (HMMA latency hidden).
// ============================================================================
#define NKT    256
#define ST_ALO 10240u
#define ST_BHI 20480u
#define ST_BLO 28672u
#define STAGE  36864u
#define G1_SMEM (2 * 36864)

__global__ void __launch_bounds__(256)
hmma_gemm1_kernel(const __nv_bfloat16* __restrict__ Ahi,
                  const __nv_bfloat16* __restrict__ Alo,
                  const float* __restrict__ W,
                  float* __restrict__ C)
{
    extern __shared__ char smemraw[];
    const uint32_t sbase = smem_to_u32(smemraw);

    const int tid  = threadIdx.x;
    const int lane = tid & 31;
    const int wid  = tid >> 5;
    const int wm   = wid & 3;
    const int wn   = wid >> 2;
    const int m0   = blockIdx.x * 128;
    const int n0   = blockIdx.y * 128;

    const int ar0 = tid >> 2,          ac0 = tid & 3;
    const int ar1 = (tid + 256) >> 2,  ac1 = tid & 3;
    const __nv_bfloat16* pAh0 = Ahi + (size_t)(m0 + ar0) * NFEAT + ac0 * 8;
    const __nv_bfloat16* pAh1 = Ahi + (size_t)(m0 + ar1) * NFEAT + ac1 * 8;
    const __nv_bfloat16* pAl0 = Alo + (size_t)(m0 + ar0) * NFEAT + ac0 * 8;
    const __nv_bfloat16* pAl1 = Alo + (size_t)(m0 + ar1) * NFEAT + ac1 * 8;
    const uint32_t aw0 = (uint32_t)(ar0 * 80 + ac0 * 16);
    const uint32_t aw1 = (uint32_t)(ar1 * 80 + ac1 * 16);

    const int bk0 = tid >> 4,         bn0 = tid & 15;
    const int bk1 = (tid + 256) >> 4, bn1 = tid & 15;
    const float* pB0 = W + (size_t)bk0 * NHID + n0 + bn0 * 8;
    const float* pB1 = W + (size_t)bk1 * NHID + n0 + bn1 * 8;
    const uint32_t bw0 = (uint32_t)(bk0 * 256 + ((bn0 ^ (bk0 & 7)) << 4));
    const uint32_t bw1 = (uint32_t)(bk1 * 256 + ((bn1 ^ (bk1 & 7)) << 4));

    uint32_t adA[2], adB[4];
#pragma unroll
    for (int mf = 0; mf < 2; mf++)
        adA[mf] = (uint32_t)((wm * 32 + mf * 16 + (lane & 15)) * 80 + (lane >> 4) * 16);
    {
        const int krb = (lane & 7) + ((lane >> 4) << 3);
#pragma unroll
        for (int g = 0; g < 4; g++) {
            int nch = wn * 8 + g * 2 + ((lane >> 3) & 1);
            adB[g] = (uint32_t)(krb * 256 + ((nch ^ (krb & 7)) << 4));
        }
    }

    float acc[2][8][4];
#pragma unroll
    for (int i = 0; i < 2; i++)
#pragma unroll
        for (int j = 0; j < 8; j++)
#pragma unroll
            for (int q = 0; q < 4; q++) acc[i][j][q] = 0.f;

    uint4  ra[4];
    float4 rb[4];

    auto load_regs = [&]() {
        ra[0] = *(const uint4*)pAh0;  ra[1] = *(const uint4*)pAh1;
        ra[2] = *(const uint4*)pAl0;  ra[3] = *(const uint4*)pAl1;
        rb[0] = *(const float4*)pB0;  rb[1] = *(const float4*)(pB0 + 4);
        rb[2] = *(const float4*)pB1;  rb[3] = *(const float4*)(pB1 + 4);
        pAh0 += 32; pAh1 += 32; pAl0 += 32; pAl1 += 32;
        pB0 += (size_t)32 * NHID; pB1 += (size_t)32 * NHID;
    };

    auto store_smem = [&](uint32_t buf) {
        const uint32_t sb = sbase + buf * STAGE;
        sts128(sb + aw0, ra[0]);
        sts128(sb + aw1, ra[1]);
        sts128(sb + ST_ALO + aw0, ra[2]);
        sts128(sb + ST_ALO + aw1, ra[3]);
        uint4 h, l;
        split8(rb[0], rb[1], h, l);
        sts128(sb + ST_BHI + bw0, h);
        sts128(sb + ST_BLO + bw0, l);
        split8(rb[2], rb[3], h, l);
        sts128(sb + ST_BHI + bw1, h);
        sts128(sb + ST_BLO + bw1, l);
    };

    load_regs();
    store_smem(0);
    __syncthreads();

    uint32_t buf = 0;
    for (int t = 0; t < NKT; t++) {
        const bool more = (t + 1 < NKT);
        if (more) load_regs();

        const uint32_t sb = sbase + buf * STAGE;
#pragma unroll
        for (int s = 0; s < 2; s++) {
            uint32_t ah[2][4], al[2][4];
            uint32_t bh[4][4], bl[4][4];
            ldsm4(ah[0], sb + adA[0] + s * 32);
            ldsm4(ah[1], sb + adA[1] + s * 32);
            ldsm4(al[0], sb + ST_ALO + adA[0] + s * 32);
            ldsm4(al[1], sb + ST_ALO + adA[1] + s * 32);
#pragma unroll
            for (int g = 0; g < 4; g++) {
                ldsm4t(bh[g], sb + ST_BHI + adB[g] + s * 4096);
                ldsm4t(bl[g], sb + ST_BLO + adB[g] + s * 4096);
            }
            // term 1: Ahi * Bhi  (16 independent MMAs)
#pragma unroll
            for (int g = 0; g < 4; g++)
#pragma unroll
                for (int mf = 0; mf < 2; mf++) {
                    mma_bf16(acc[mf][2 * g],     ah[mf], bh[g][0], bh[g][2]);
                    mma_bf16(acc[mf][2 * g + 1], ah[mf], bh[g][1], bh[g][3]);
                }
            // term 2: Alo * Bhi
#pragma unroll
            for (int g = 0; g < 4; g++)
#pragma unroll
                for (int mf = 0; mf < 2; mf++) {
                    mma_bf16(acc[mf][2 * g],     al[mf], bh[g][0], bh[g][2]);
                    mma_bf16(acc[mf][2 * g + 1], al[mf], bh[g][1], bh[g][3]);
                }
            // term 3: Ahi * Blo
#pragma unroll
            for (int g = 0; g < 4; g++)
#pragma unroll
                for (int mf = 0; mf < 2; mf++) {
                    mma_bf16(acc[mf][2 * g],     ah[mf], bl[g][0], bl[g][2]);
                    mma_bf16(acc[mf][2 * g + 1], ah[mf], bl[g][1], bl[g][3]);
                }
        }

        if (more) {
            store_smem(buf ^ 1u);
            __syncthreads();
            buf ^= 1u;
        }
    }

    const int er = lane >> 2;
    const int ec = (lane & 3) * 2;
#pragma unroll
    for (int mf = 0; mf < 2; mf++) {
        const int mb = m0 + wm * 32 + mf * 16 + er;
#pragma unroll
        for (int g8 = 0; g8 < 8; g8++) {
            const int n = n0 + wn * 64 + g8 * 8 + ec;
            if (mb < M_NODES)
                *(float2*)(C + (size_t)mb * NHID + n) =
                    make_float2(acc[mf][g8][0], acc[mf][g8][1]);
            if (mb + 8 < M_NODES)
                *(float2*)(C + (size_t)(mb + 8) * NHID + n) =
                    make_float2(acc[mf][g8][2], acc[mf][g8][3]);
        }
    }
}

// ============================================================================
// GEMM2: h1 = relu(adj[208,208] @ s1[208,8192] + gc1_b)
// Smem-resident rank-1: adj strip [104][208] + s1 tile [208][64].
// ============================================================================
#define G2_SMEM (104 * 208 * 4 + 208 * 64 * 4)   // 139776 B

__global__ void __launch_bounds__(256, 1)
gemm2_kernel(const float* __restrict__ adj, const float* __restrict__ s1,
             const float* __restrict__ bias, float* __restrict__ h1)
{
    extern __shared__ float g2s[];
    float* adjs = g2s;                    // [104][208]
    float* s1s  = g2s + 104 * 208;        // [208][64]

    const int tid = threadIdx.x;
    const int n0 = blockIdx.x * 64;
    const int m0 = blockIdx.y * 104;

    for (int idx = tid; idx < 208 * 16; idx += 256) {
        int r = idx >> 4, c = (idx & 15) * 4;
        *(float4*)(s1s + r * 64 + c) =
            *(const float4*)(s1 + (size_t)r * NHID + n0 + c);
    }
    for (int idx = tid; idx < 104 * 52; idx += 256) {
        int r = idx / 52, c = (idx % 52) * 4;
        *(float4*)(adjs + r * 208 + c) =
            *(const float4*)(adj + (size_t)(m0 + r) * M_NODES + c);
    }
    __syncthreads();

    const int tm = tid >> 5;
    const int tn = tid & 31;

    float acc[13][2];
#pragma unroll
    for (int i = 0; i < 13; i++) { acc[i][0] = 0.f; acc[i][1] = 0.f; }

    const float* abase = adjs + tm * 13 * 208;
    const float* sbase = s1s + tn * 2;

#pragma unroll 4
    for (int k = 0; k < M_NODES; k++) {
        const float2 sv = *(const float2*)(sbase + k * 64);
#pragma unroll
        for (int i = 0; i < 13; i++) {
            const float a = abase[i * 208 + k];
            acc[i][0] = fmaf(a, sv.x, acc[i][0]);
            acc[i][1] = fmaf(a, sv.y, acc[i][1]);
        }
    }

    const float b0 = bias[n0 + tn * 2];
    const float b1 = bias[n0 + tn * 2 + 1];
#pragma unroll
    for (int i = 0; i < 13; i++) {
        const int m = m0 + tm * 13 + i;
        float v0 = acc[i][0] + b0;
        float v1 = acc[i][1] + b1;
        v0 = v0 > 0.f ? v0 : 0.f;
        v1 = v1 > 0.f ? v1 : 0.f;
        *(float2*)(h1 + (size_t)m * NHID + n0 + tn * 2) = make_float2(v0, v1);
    }
}

// ---------------------------------------------------------------------------
// GEMM3 split-K (R14 version): grid (52, 16), 256 thr = 16 k x 16 n-quads,
// 4 m-rows per block, float4 W loads.
// ---------------------------------------------------------------------------
__global__ void __launch_bounds__(256, 4)
gemm3_split_kernel(const float* __restrict__ h1, const float* __restrict__ w2,
                   float* __restrict__ p3)
{
    const int t  = threadIdx.x;
    const int tn = t & 15;
    const int tk = t >> 4;
    const int mb = blockIdx.x * 4;
    const int kc = blockIdx.y;

    const int kbeg = kc * 512 + tk * 32;
    const float* h0 = h1 + (size_t)mb * NHID;

    float acc[4][4];
#pragma unroll
    for (int m = 0; m < 4; m++)
#pragma unroll
        for (int j = 0; j < 4; j++) acc[m][j] = 0.f;

#pragma unroll 4
    for (int k = kbeg; k < kbeg + 32; k++) {
        const float4 w = *(const float4*)(w2 + (size_t)k * NCLASS + tn * 4);
#pragma unroll
        for (int m = 0; m < 4; m++) {
            const float h = h0[(size_t)m * NHID + k];
            acc[m][0] = fmaf(h, w.x, acc[m][0]);
            acc[m][1] = fmaf(h, w.y, acc[m][1]);
            acc[m][2] = fmaf(h, w.z, acc[m][2]);
            acc[m][3] = fmaf(h, w.w, acc[m][3]);
        }
    }

    __shared__ float red[16][4][64];
#pragma unroll
    for (int m = 0; m < 4; m++)
        *(float4*)&red[tk][m][tn * 4] =
            make_float4(acc[m][0], acc[m][1], acc[m][2], acc[m][3]);
    __syncthreads();

    const int om = t >> 6, on = t & 63;
    float s = 0.f;
#pragma unroll
    for (int p = 0; p < 16; p++) s += red[p][om][on];
    p3[(size_t)kc * (M_NODES * NCLASS) + (size_t)(mb + om) * NCLASS + on] = s;
}

__global__ void __launch_bounds__(256, 4)
gemm3_reduce_kernel(const float* __restrict__ p3, float* __restrict__ out)
{
    const int i = blockIdx.x * 256 + threadIdx.x;
    if (i >= M_NODES * NCLASS) return;
    float s = 0.f;
#pragma unroll
    for (int p = 0; p < G3_SPLIT; p++)
        s += p3[(size_t)p * (M_NODES * NCLASS) + i];
    out[i] = s;
}

// ---------------------------------------------------------------------------
// GEMM4: h2 = relu(adj[208,208] @ s2[208,64] + b2[64])
// ---------------------------------------------------------------------------
__global__ void __launch_bounds__(256, 4)
gemm4_kernel(const float* __restrict__ adj, const float* __restrict__ s2,
             const float* __restrict__ b, float* __restrict__ h2)
{
    const int t = threadIdx.x;
    const int n = t & 63;
    const int m = blockIdx.x * 4 + (t >> 6);

    float acc = 0.f;
    const float* ar = adj + (size_t)m * M_NODES;
#pragma unroll 8
    for (int k = 0; k < M_NODES; k++)
        acc = fmaf(ar[k], s2[(size_t)k * NCLASS + n], acc);

    float v = acc + b[n];
    h2[(size_t)m * NCLASS + n] = v > 0.f ? v : 0.f;
}

// ---------------------------------------------------------------------------
// FC1: v1[128] = relu(fc1_w[128,13312] @ h2.flat + fc1_b)
// ---------------------------------------------------------------------------
__global__ void __launch_bounds__(256, 1)
fc1_kernel(const float* __restrict__ w, const float* __restrict__ b,
           const float* __restrict__ h2, float* __restrict__ v1)
{
    const int r = blockIdx.x;
    const int t = threadIdx.x;
    const float* wr = w + (size_t)r * (M_NODES * NCLASS);

    float p = 0.f;
    for (int i = t; i < M_NODES * NCLASS; i += 256)
        p = fmaf(wr[i], h2[i], p);

    __shared__ float red[256];
    red[t] = p;
    __syncthreads();
#pragma unroll
    for (int s = 128; s > 0; s >>= 1) {
        if (t < s) red[t] += red[t + s];
        __syncthreads();
    }
    if (t == 0) {
        float v = red[0] + b[r];
        v1[r] = v > 0.f ? v : 0.f;
    }
}

// ---------------------------------------------------------------------------
// Head
// ---------------------------------------------------------------------------
__global__ void __launch_bounds__(128, 1)
head_kernel(const float* __restrict__ fc2w, const float* __restrict__ fc2b,
            const float* __restrict__ fc3w, const float* __restrict__ fc3b,
            const float* __restrict__ v1, float* __restrict__ out)
{
    __shared__ float v1s[128];
    __shared__ float v2s[32];
    const int t = threadIdx.x;

    v1s[t] = v1[t];
    __syncthreads();

    if (t < 32) {
        float a = 0.f;
#pragma unroll 4
        for (int j = 0; j < 128; j++)
            a = fmaf(fc2w[t * 128 + j], v1s[j], a);
        a += fc2b[t];
        v2s[t] = a > 0.f ? a : 0.f;
    }
    __syncthreads();

    if (t == 0) {
        float s = fc3b[0];
#pragma unroll
        for (int i = 0; i < 32; i++)
            s = fmaf(fc3w[i], v2s[i], s);
        out[0] = 1.0f / (1.0f + expf(-s));
    }
}

// ---------------------------------------------------------------------------
// Launch
// ---------------------------------------------------------------------------
extern "C" void kernel_launch(void* const* d_in, const int* in_sizes, int n_in,
                              void* d_out, int out_size)
{
    (void)in_sizes; (void)n_in; (void)out_size;

    const float* x     = (const float*)d_in[0];
    const float* adj   = (const float*)d_in[1];
    const float* gc1_w = (const float*)d_in[2];
    const float* gc1_b = (const float*)d_in[3];
    const float* gc2_w = (const float*)d_in[4];
    const float* gc2_b = (const float*)d_in[5];
    const float* fc1_w = (const float*)d_in[6];
    const float* fc1_b = (const float*)d_in[7];
    const float* fc2_w = (const float*)d_in[8];
    const float* fc2_b = (const float*)d_in[9];
    const float* fc3_w = (const float*)d_in[10];
    const float* fc3_b = (const float*)d_in[11];
    float* out = (float*)d_out;

    float *s1, *h1, *s2, *h2, *v1, *p3;
    __nv_bfloat16 *Ahi, *Alo;
    cudaGetSymbolAddress((void**)&s1, g_s1);
    cudaGetSymbolAddress((void**)&h1, g_h1);
    cudaGetSymbolAddress((void**)&s2, g_s2);
    cudaGetSymbolAddress((void**)&h2, g_h2);
    cudaGetSymbolAddress((void**)&v1, g_v1);
    cudaGetSymbolAddress((void**)&p3, g_p3);
    cudaGetSymbolAddress((void**)&Ahi, g_Ahi);
    cudaGetSymbolAddress((void**)&Alo, g_Alo);

    cudaFuncSetAttribute(hmma_gemm1_kernel,
                         cudaFuncAttributeMaxDynamicSharedMemorySize, G1_SMEM);
    cudaFuncSetAttribute(gemm2_kernel,
                         cudaFuncAttributeMaxDynamicSharedMemorySize, G2_SMEM);

    // split x -> bf16 hi/lo (padded to 256 rows)
    convx_kernel<<<(M_PAD * NFEAT / 2) / 256, 256>>>(x, Ahi, Alo);

    // s1 = x @ gc1_w  (HMMA, 3-term bf16 split; W split in-kernel)
    hmma_gemm1_kernel<<<dim3(2, NHID / 128), 256, G1_SMEM>>>(Ahi, Alo, gc1_w, s1);

    // h1 = relu(adj @ s1 + gc1_b)  (smem-resident rank-1)
    gemm2_kernel<<<dim3(NHID / 64, 2), 256, G2_SMEM>>>(adj, s1, gc1_b, h1);

    // s2 = h1 @ gc2_w  (split-K + reduce)
    gemm3_split_kernel<<<dim3(M_NODES / 4, G3_SPLIT), 256>>>(h1, gc2_w, p3);
    gemm3_reduce_kernel<<<(M_NODES * NCLASS + 255) / 256, 256>>>(p3, s2);
    // h2 = relu(adj @ s2 + gc2_b)
    gemm4_kernel<<<M_NODES / 4, 256>>>(adj, s2, gc2_b, h2);
    // v1 = relu(fc1_w @ h2.flat + fc1_b)
    fc1_kernel<<<128, 256>>>(fc1_w, fc1_b, h2, v1);
    // out = sigmoid(fc3 @ relu(fc2 @ v1 + b2) + b3)
    head_kernel<<<1, 128>>>(fc2_w, fc2_b, fc3_w, fc3_b, v1, out);
}